// round 2
// baseline (speedup 1.0000x reference)
#include <cuda_runtime.h>

#define N_E    8192
#define E_DIM  256
#define N_TOK  32768            // 16 * 2048
#define BM     128
#define BN     128
#define BK     16
#define LDP    132              // padded leading dim for smem tiles

// ---- output layout (concat of reference return tuple, f32) ----
#define OFF_ZQ    0
#define OFF_IDX   8388608
#define OFF_LOSS  8421376
#define OFF_NEMB  8421377

// ---- device scratch (no allocations allowed) ----
__device__ float g_bins[N_E];
__device__ float g_dw[N_E * E_DIM];
__device__ float g_eN[N_E];
__device__ float g_loss;

// ============================================================
// K1: zero scratch + ||e||^2 (sequential, mul-then-add like jnp.sum(e*e))
// ============================================================
__global__ void k_init(const float* __restrict__ emb) {
    int gid = blockIdx.x * blockDim.x + threadIdx.x;
    if (gid < N_E * E_DIM) g_dw[gid] = 0.0f;
    if (gid < N_E) {
        g_bins[gid] = 0.0f;
        const float* e = emb + gid * E_DIM;
        float s = 0.0f;
        #pragma unroll 8
        for (int k = 0; k < E_DIM; k++)
            s = __fadd_rn(s, __fmul_rn(e[k], e[k]));
        g_eN[gid] = s;
    }
    if (gid == 0) g_loss = 0.0f;
}

// ============================================================
// K2: fused distance-GEMM + argmin + epilogue
//   block: 128 z-rows vs all 8192 codes, 256 threads, 8x8 per thread
// ============================================================
__global__ __launch_bounds__(256, 2)
void k_main(const float* __restrict__ z, const float* __restrict__ emb,
            float* __restrict__ out_zq, float* __restrict__ out_idx) {
    __shared__ float sm[4480];           // 17.9 KB
    float* As   = sm;                    // [BK][LDP]  (0 .. 2111)
    float* Bs   = sm + 2112;             // [BK][LDP]  (2112 .. 4223)
    float* eNs  = sm + 4224;             // [128]
    float* znS  = sm + 4352;             // [128]
    float* redD = sm;                    // [128*16]  (reuse, after GEMM)
    int*   redI = (int*)(sm + 2048);     // [128*16]
    int*   bIdx = (int*)(sm + 4224);     // [128]     (reuse eNs, after reduce)

    const int tid = threadIdx.x;
    const int tx  = tid & 15;
    const int ty  = tid >> 4;
    const int row0 = blockIdx.x * BM;

    // per-row ||z||^2 : sequential mul-then-add (mirrors jnp.sum(z*z, axis=1))
    if (tid < BM) {
        const float* zr = z + (size_t)(row0 + tid) * E_DIM;
        float s = 0.0f;
        #pragma unroll 8
        for (int k = 0; k < E_DIM; k++)
            s = __fadd_rn(s, __fmul_rn(zr[k], zr[k]));
        znS[tid] = s;
    }
    __syncthreads();

    float bestD[8];
    int   bestI[8];
    #pragma unroll
    for (int i = 0; i < 8; i++) { bestD[i] = 3.402823466e38f; bestI[i] = 0; }

    for (int nt = 0; nt < N_E / BN; nt++) {
        if (tid < BN) eNs[tid] = g_eN[nt * BN + tid];

        float acc[8][8];
        #pragma unroll
        for (int i = 0; i < 8; i++)
            #pragma unroll
            for (int j = 0; j < 8; j++) acc[i][j] = 0.0f;

        for (int kt = 0; kt < E_DIM / BK; kt++) {
            // load A (z) and B (emb) chunks, transposed into smem
            #pragma unroll
            for (int u = 0; u < 2; u++) {
                int v  = tid + u * 256;          // 0..511
                int r  = v >> 2;                  // 0..127
                int c4 = (v & 3) * 4;             // 0,4,8,12
                float4 ta = *(const float4*)(z   + (size_t)(row0 + r) * E_DIM + kt * BK + c4);
                float4 tb = *(const float4*)(emb + (size_t)(nt * BN + r) * E_DIM + kt * BK + c4);
                As[(c4 + 0) * LDP + r] = ta.x;
                As[(c4 + 1) * LDP + r] = ta.y;
                As[(c4 + 2) * LDP + r] = ta.z;
                As[(c4 + 3) * LDP + r] = ta.w;
                Bs[(c4 + 0) * LDP + r] = tb.x;
                Bs[(c4 + 1) * LDP + r] = tb.y;
                Bs[(c4 + 2) * LDP + r] = tb.z;
                Bs[(c4 + 3) * LDP + r] = tb.w;
            }
            __syncthreads();

            #pragma unroll
            for (int k = 0; k < BK; k++) {
                float a[8], b[8];
                *(float4*)(a)     = *(const float4*)&As[k * LDP + ty * 8];
                *(float4*)(a + 4) = *(const float4*)&As[k * LDP + ty * 8 + 4];
                *(float4*)(b)     = *(const float4*)&Bs[k * LDP + tx * 8];
                *(float4*)(b + 4) = *(const float4*)&Bs[k * LDP + tx * 8 + 4];
                #pragma unroll
                for (int i = 0; i < 8; i++)
                    #pragma unroll
                    for (int j = 0; j < 8; j++)
                        acc[i][j] = __fmaf_rn(a[i], b[j], acc[i][j]);
            }
            __syncthreads();
        }

        // distances + running argmin; code index ascending => strict < keeps lowest
        #pragma unroll
        for (int j = 0; j < 8; j++) {
            int   c  = nt * BN + tx * 8 + j;
            float en = eNs[tx * 8 + j];
            #pragma unroll
            for (int i = 0; i < 8; i++) {
                float d = __fsub_rn(__fadd_rn(znS[ty * 8 + i], en),
                                    __fmul_rn(2.0f, acc[i][j]));
                if (d < bestD[i]) { bestD[i] = d; bestI[i] = c; }
            }
        }
        __syncthreads();   // protect eNs for next tile
    }

    // cross-thread argmin reduce (16 column-groups per row)
    #pragma unroll
    for (int i = 0; i < 8; i++) {
        redD[(ty * 8 + i) * 16 + tx] = bestD[i];
        redI[(ty * 8 + i) * 16 + tx] = bestI[i];
    }
    __syncthreads();

    if (tid < BM) {
        float bd = redD[tid * 16];
        int   bi = redI[tid * 16];
        #pragma unroll
        for (int t = 1; t < 16; t++) {
            float d  = redD[tid * 16 + t];
            int   ii = redI[tid * 16 + t];
            if (d < bd || (d == bd && ii < bi)) { bd = d; bi = ii; }
        }
        bIdx[tid] = bi;
        out_idx[row0 + tid] = (float)bi;
        atomicAdd(&g_bins[bi], 1.0f);
    }
    __syncthreads();

    // epilogue: gather z_q, straight-through write, loss partial, dw atomics
    {
        int r = tid >> 1;
        int h = tid & 1;
        int bi = bIdx[r];
        const float4* zr = (const float4*)(z   + (size_t)(row0 + r) * E_DIM + h * 128);
        const float4* er = (const float4*)(emb + (size_t)bi * E_DIM + h * 128);
        float4*       oq = (float4*)(out_zq + (size_t)(row0 + r) * E_DIM + h * 128);
        float*        dw = g_dw + (size_t)bi * E_DIM + h * 128;
        float ls = 0.0f;
        #pragma unroll 4
        for (int d4 = 0; d4 < 32; d4++) {
            float4 zv = zr[d4];
            float4 ev = er[d4];
            float4 o;
            o.x = __fadd_rn(zv.x, __fsub_rn(ev.x, zv.x));
            o.y = __fadd_rn(zv.y, __fsub_rn(ev.y, zv.y));
            o.z = __fadd_rn(zv.z, __fsub_rn(ev.z, zv.z));
            o.w = __fadd_rn(zv.w, __fsub_rn(ev.w, zv.w));
            oq[d4] = o;
            float dx = __fsub_rn(zv.x, ev.x);
            float dy = __fsub_rn(zv.y, ev.y);
            float dz = __fsub_rn(zv.z, ev.z);
            float dwc = __fsub_rn(zv.w, ev.w);
            ls = __fadd_rn(ls, __fmul_rn(dx, dx));
            ls = __fadd_rn(ls, __fmul_rn(dy, dy));
            ls = __fadd_rn(ls, __fmul_rn(dz, dz));
            ls = __fadd_rn(ls, __fmul_rn(dwc, dwc));
            atomicAdd(dw + d4 * 4 + 0, zv.x);
            atomicAdd(dw + d4 * 4 + 1, zv.y);
            atomicAdd(dw + d4 * 4 + 2, zv.z);
            atomicAdd(dw + d4 * 4 + 3, zv.w);
        }
        // block-level loss reduction (reuse sm[0..255])
        __syncthreads();
        sm[tid] = ls;
        __syncthreads();
        for (int s = 128; s > 0; s >>= 1) {
            if (tid < s) sm[tid] += sm[tid + s];
            __syncthreads();
        }
        if (tid == 0) atomicAdd(&g_loss, sm[0]);
    }
}

// ============================================================
// K3: finalize new_embeddings + loss
// ============================================================
__global__ void k_final(float* __restrict__ out_nemb, float* __restrict__ out_loss) {
    int gid = blockIdx.x * blockDim.x + threadIdx.x;
    if (gid == 0) {
        float mean = __fdiv_rn(g_loss, 8388608.0f);
        out_loss[0] = __fmul_rn(0.25f, mean);
    }
    if (gid < N_E * E_DIM) {
        int k = gid >> 8;                       // E_DIM = 256
        float b   = g_bins[k];
        float t1  = __fadd_rn(b, 1e-5f);
        float den = 32768.08192f;               // fl32(n + N_E*EPSILON), n = 32768
        float cl  = __fmul_rn(__fdiv_rn(t1, den), 32768.0f);
        out_nemb[gid] = __fdiv_rn(g_dw[gid], cl);
    }
}

// ============================================================
extern "C" void kernel_launch(void* const* d_in, const int* in_sizes, int n_in,
                              void* d_out, int out_size) {
    const float* z   = (const float*)d_in[0];
    const float* emb = (const float*)d_in[1];
    float* out = (float*)d_out;

    float* out_zq   = out + OFF_ZQ;
    float* out_idx  = out + OFF_IDX;
    float* out_loss = out + OFF_LOSS;
    float* out_nemb = out + OFF_NEMB;

    k_init<<<8192, 256>>>(emb);
    k_main<<<N_TOK / BM, 256>>>(z, emb, out_zq, out_idx);
    k_final<<<8192, 256>>>(out_nemb, out_loss);
}

// round 4
// speedup vs baseline: 1.0018x; 1.0018x over previous
#include <cuda_runtime.h>

#define N_E    8192
#define E_DIM  256
#define N_TOK  32768            // 16 * 2048
#define BM     128
#define BN     128
#define BK     16
#define LDP    132              // padded leading dim for smem tiles

// ---- output layout (concat of reference return tuple, f32) ----
#define OFF_ZQ    0
#define OFF_IDX   8388608
#define OFF_LOSS  8421376
#define OFF_NEMB  8421377

// ---- device scratch (no allocations allowed) ----
__device__ float g_bins[N_E];
__device__ float g_dw[N_E * E_DIM];
__device__ float g_eN[N_E];
__device__ float g_loss;

// ============================================================
// K1: zero scratch + ||e||^2 (sequential, mul-then-add like jnp.sum(e*e))
// ============================================================
__global__ void k_init(const float* __restrict__ emb) {
    int gid = blockIdx.x * blockDim.x + threadIdx.x;
    if (gid < N_E * E_DIM) g_dw[gid] = 0.0f;
    if (gid < N_E) {
        g_bins[gid] = 0.0f;
        const float* e = emb + gid * E_DIM;
        float s = 0.0f;
        #pragma unroll 8
        for (int k = 0; k < E_DIM; k++)
            s = __fadd_rn(s, __fmul_rn(e[k], e[k]));
        g_eN[gid] = s;
    }
    if (gid == 0) g_loss = 0.0f;
}

// ============================================================
// K2: fused distance-GEMM + argmin + epilogue
//   block: 128 z-rows vs all 8192 codes, 256 threads, 8x8 per thread
// ============================================================
__global__ __launch_bounds__(256, 2)
void k_main(const float* __restrict__ z, const float* __restrict__ emb,
            float* __restrict__ out_zq, float* __restrict__ out_idx) {
    __shared__ float sm[4480];           // 17.9 KB
    float* As   = sm;                    // [BK][LDP]  (0 .. 2111)
    float* Bs   = sm + 2112;             // [BK][LDP]  (2112 .. 4223)
    float* eNs  = sm + 4224;             // [128]
    float* znS  = sm + 4352;             // [128]
    float* redD = sm;                    // [128*16]  (reuse, after GEMM)
    int*   redI = (int*)(sm + 2048);     // [128*16]
    int*   bIdx = (int*)(sm + 4224);     // [128]     (reuse eNs, after reduce)

    const int tid = threadIdx.x;
    const int tx  = tid & 15;
    const int ty  = tid >> 4;
    const int row0 = blockIdx.x * BM;

    // per-row ||z||^2 : sequential mul-then-add (mirrors jnp.sum(z*z, axis=1))
    if (tid < BM) {
        const float* zr = z + (size_t)(row0 + tid) * E_DIM;
        float s = 0.0f;
        #pragma unroll 8
        for (int k = 0; k < E_DIM; k++)
            s = __fadd_rn(s, __fmul_rn(zr[k], zr[k]));
        znS[tid] = s;
    }
    __syncthreads();

    float bestD[8];
    int   bestI[8];
    #pragma unroll
    for (int i = 0; i < 8; i++) { bestD[i] = 3.402823466e38f; bestI[i] = 0; }

    for (int nt = 0; nt < N_E / BN; nt++) {
        if (tid < BN) eNs[tid] = g_eN[nt * BN + tid];

        float acc[8][8];
        #pragma unroll
        for (int i = 0; i < 8; i++)
            #pragma unroll
            for (int j = 0; j < 8; j++) acc[i][j] = 0.0f;

        for (int kt = 0; kt < E_DIM / BK; kt++) {
            // load A (z) and B (emb) chunks, transposed into smem
            #pragma unroll
            for (int u = 0; u < 2; u++) {
                int v  = tid + u * 256;          // 0..511
                int r  = v >> 2;                  // 0..127
                int c4 = (v & 3) * 4;             // 0,4,8,12
                float4 ta = *(const float4*)(z   + (size_t)(row0 + r) * E_DIM + kt * BK + c4);
                float4 tb = *(const float4*)(emb + (size_t)(nt * BN + r) * E_DIM + kt * BK + c4);
                As[(c4 + 0) * LDP + r] = ta.x;
                As[(c4 + 1) * LDP + r] = ta.y;
                As[(c4 + 2) * LDP + r] = ta.z;
                As[(c4 + 3) * LDP + r] = ta.w;
                Bs[(c4 + 0) * LDP + r] = tb.x;
                Bs[(c4 + 1) * LDP + r] = tb.y;
                Bs[(c4 + 2) * LDP + r] = tb.z;
                Bs[(c4 + 3) * LDP + r] = tb.w;
            }
            __syncthreads();

            #pragma unroll
            for (int k = 0; k < BK; k++) {
                float a[8], b[8];
                *(float4*)(a)     = *(const float4*)&As[k * LDP + ty * 8];
                *(float4*)(a + 4) = *(const float4*)&As[k * LDP + ty * 8 + 4];
                *(float4*)(b)     = *(const float4*)&Bs[k * LDP + tx * 8];
                *(float4*)(b + 4) = *(const float4*)&Bs[k * LDP + tx * 8 + 4];
                #pragma unroll
                for (int i = 0; i < 8; i++)
                    #pragma unroll
                    for (int j = 0; j < 8; j++)
                        acc[i][j] = __fmaf_rn(a[i], b[j], acc[i][j]);
            }
            __syncthreads();
        }

        // distances + running argmin; code index ascending => strict < keeps lowest
        #pragma unroll
        for (int j = 0; j < 8; j++) {
            int   c  = nt * BN + tx * 8 + j;
            float en = eNs[tx * 8 + j];
            #pragma unroll
            for (int i = 0; i < 8; i++) {
                float d = __fsub_rn(__fadd_rn(znS[ty * 8 + i], en),
                                    __fmul_rn(2.0f, acc[i][j]));
                if (d < bestD[i]) { bestD[i] = d; bestI[i] = c; }
            }
        }
        __syncthreads();   // protect eNs for next tile
    }

    // cross-thread argmin reduce (16 column-groups per row)
    #pragma unroll
    for (int i = 0; i < 8; i++) {
        redD[(ty * 8 + i) * 16 + tx] = bestD[i];
        redI[(ty * 8 + i) * 16 + tx] = bestI[i];
    }
    __syncthreads();

    if (tid < BM) {
        float bd = redD[tid * 16];
        int   bi = redI[tid * 16];
        #pragma unroll
        for (int t = 1; t < 16; t++) {
            float d  = redD[tid * 16 + t];
            int   ii = redI[tid * 16 + t];
            if (d < bd || (d == bd && ii < bi)) { bd = d; bi = ii; }
        }
        bIdx[tid] = bi;
        out_idx[row0 + tid] = (float)bi;
        atomicAdd(&g_bins[bi], 1.0f);
    }
    __syncthreads();

    // epilogue: gather z_q, straight-through write, loss partial, dw atomics
    {
        int r = tid >> 1;
        int h = tid & 1;
        int bi = bIdx[r];
        const float4* zr = (const float4*)(z   + (size_t)(row0 + r) * E_DIM + h * 128);
        const float4* er = (const float4*)(emb + (size_t)bi * E_DIM + h * 128);
        float4*       oq = (float4*)(out_zq + (size_t)(row0 + r) * E_DIM + h * 128);
        float*        dw = g_dw + (size_t)bi * E_DIM + h * 128;
        float ls = 0.0f;
        #pragma unroll 4
        for (int d4 = 0; d4 < 32; d4++) {
            float4 zv = zr[d4];
            float4 ev = er[d4];
            float4 o;
            o.x = __fadd_rn(zv.x, __fsub_rn(ev.x, zv.x));
            o.y = __fadd_rn(zv.y, __fsub_rn(ev.y, zv.y));
            o.z = __fadd_rn(zv.z, __fsub_rn(ev.z, zv.z));
            o.w = __fadd_rn(zv.w, __fsub_rn(ev.w, zv.w));
            oq[d4] = o;
            float dx = __fsub_rn(zv.x, ev.x);
            float dy = __fsub_rn(zv.y, ev.y);
            float dz = __fsub_rn(zv.z, ev.z);
            float dwc = __fsub_rn(zv.w, ev.w);
            ls = __fadd_rn(ls, __fmul_rn(dx, dx));
            ls = __fadd_rn(ls, __fmul_rn(dy, dy));
            ls = __fadd_rn(ls, __fmul_rn(dz, dz));
            ls = __fadd_rn(ls, __fmul_rn(dwc, dwc));
            atomicAdd(dw + d4 * 4 + 0, zv.x);
            atomicAdd(dw + d4 * 4 + 1, zv.y);
            atomicAdd(dw + d4 * 4 + 2, zv.z);
            atomicAdd(dw + d4 * 4 + 3, zv.w);
        }
        // block-level loss reduction (reuse sm[0..255])
        __syncthreads();
        sm[tid] = ls;
        __syncthreads();
        for (int s = 128; s > 0; s >>= 1) {
            if (tid < s) sm[tid] += sm[tid + s];
            __syncthreads();
        }
        if (tid == 0) atomicAdd(&g_loss, sm[0]);
    }
}

// ============================================================
// K3: finalize new_embeddings + loss
// ============================================================
__global__ void k_final(float* __restrict__ out_nemb, float* __restrict__ out_loss) {
    int gid = blockIdx.x * blockDim.x + threadIdx.x;
    if (gid == 0) {
        float mean = __fdiv_rn(g_loss, 8388608.0f);
        out_loss[0] = __fmul_rn(0.25f, mean);
    }
    if (gid < N_E * E_DIM) {
        int k = gid >> 8;                       // E_DIM = 256
        float b   = g_bins[k];
        float t1  = __fadd_rn(b, 1e-5f);
        float den = 32768.08192f;               // fl32(n + N_E*EPSILON), n = 32768
        float cl  = __fmul_rn(__fdiv_rn(t1, den), 32768.0f);
        out_nemb[gid] = __fdiv_rn(g_dw[gid], cl);
    }
}

// ============================================================
extern "C" void kernel_launch(void* const* d_in, const int* in_sizes, int n_in,
                              void* d_out, int out_size) {
    const float* z   = (const float*)d_in[0];
    const float* emb = (const float*)d_in[1];
    float* out = (float*)d_out;

    float* out_zq   = out + OFF_ZQ;
    float* out_idx  = out + OFF_IDX;
    float* out_loss = out + OFF_LOSS;
    float* out_nemb = out + OFF_NEMB;

    k_init<<<8192, 256>>>(emb);
    k_main<<<N_TOK / BM, 256>>>(z, emb, out_zq, out_idx);
    k_final<<<8192, 256>>>(out_nemb, out_loss);
}

// round 8
// speedup vs baseline: 1.4352x; 1.4326x over previous
#include <cuda_runtime.h>
#include <cuda_bf16.h>
#include <cstdint>

#define N_E    8192
#define E_DIM  256
#define N_TOK  32768

#define OFF_ZQ   0
#define OFF_IDX  8388608
#define OFF_LOSS 8421376
#define OFF_NEMB 8421377

#define TH_MARGIN 3.0e-3f
#define NSTG   256               // 8192 / 32 codes per stage
#define ROWSTR 528u              // padded bf16 row stride in bytes (256*2 + 16)

// dynamic smem layout (bytes)
#define SM_AH  0u                // 128 x 528            = 67584
#define SM_AL  67584u            // 128 x 528            = 67584
#define SM_BH  135168u           // 2 stages x 32 x 528  = 33792
#define SM_BL  168960u           // 2 stages x 32 x 528  = 33792
#define SM_EN  202752u           // 2 stages x 128B
#define SM_ZN  203008u           // 128 x 4B
#define SM_DYN 203520

// ---- device scratch (no allocations allowed) ----
__device__ float g_bins[N_E];
__device__ float g_dw[N_E * E_DIM];
__device__ float g_eN[N_E];
__device__ float g_loss;
__device__ int   g_ucount;
__device__ int   g_idxi[N_TOK];
__device__ float g_zn[N_TOK];
__device__ int   g_urows[N_TOK];
__device__ int   g_ucand[N_TOK * 16];
__device__ __nv_bfloat16 g_eh[N_E * E_DIM];
__device__ __nv_bfloat16 g_el[N_E * E_DIM];

// ---------------- PTX helpers (all sm_80+ baseline features) ----------------
__device__ __forceinline__ uint32_t smem_u32(const void* p) {
    uint32_t a;
    asm("{ .reg .u64 t; cvta.to.shared.u64 t, %1; cvt.u32.u64 %0, t; }" : "=r"(a) : "l"(p));
    return a;
}
__device__ __forceinline__ void cpa16(uint32_t dst, const void* src) {
    asm volatile("cp.async.cg.shared.global [%0], [%1], 16;" :: "r"(dst), "l"(src) : "memory");
}
__device__ __forceinline__ void ldm4(uint32_t* r, uint32_t a) {
    asm volatile("ldmatrix.sync.aligned.m8n8.x4.shared.b16 {%0,%1,%2,%3}, [%4];"
                 : "=r"(r[0]), "=r"(r[1]), "=r"(r[2]), "=r"(r[3]) : "r"(a));
}
__device__ __forceinline__ void ldm2(uint32_t* r, uint32_t a) {
    asm volatile("ldmatrix.sync.aligned.m8n8.x2.shared.b16 {%0,%1}, [%2];"
                 : "=r"(r[0]), "=r"(r[1]) : "r"(a));
}
__device__ __forceinline__ void mma16816(float* c, const uint32_t* a, const uint32_t* b) {
    asm volatile(
        "mma.sync.aligned.m16n8k16.row.col.f32.bf16.bf16.f32 "
        "{%0,%1,%2,%3}, {%4,%5,%6,%7}, {%8,%9}, {%0,%1,%2,%3};"
        : "+f"(c[0]), "+f"(c[1]), "+f"(c[2]), "+f"(c[3])
        : "r"(a[0]), "r"(a[1]), "r"(a[2]), "r"(a[3]), "r"(b[0]), "r"(b[1]));
}

// ============================================================
// K1: zero scratch + ||e||^2 (exact sequential, matches reference rounding)
// ============================================================
__global__ void k_init(const float* __restrict__ emb) {
    int gid = blockIdx.x * blockDim.x + threadIdx.x;
    if (gid < N_E * E_DIM) g_dw[gid] = 0.0f;
    if (gid < N_E) {
        g_bins[gid] = 0.0f;
        const float* e = emb + (size_t)gid * E_DIM;
        float s = 0.0f;
        #pragma unroll 8
        for (int k = 0; k < E_DIM; k++) s = __fadd_rn(s, __fmul_rn(e[k], e[k]));
        g_eN[gid] = s;
    }
    if (gid == 0) { g_loss = 0.0f; g_ucount = 0; }
}

// ============================================================
// K2: bf16 hi/lo split of embeddings (row-major images)
// ============================================================
__global__ void k_prep(const float* __restrict__ emb) {
    int gid = blockIdx.x * blockDim.x + threadIdx.x;   // over N_E*E_DIM
    float e = emb[gid];
    __nv_bfloat16 h = __float2bfloat16(e);
    __nv_bfloat16 l = __float2bfloat16(__fsub_rn(e, __bfloat162float(h)));
    g_eh[gid] = h;
    g_el[gid] = l;
}

// ============================================================
// K3: mma.sync distance GEMM + per-owner top-2 argmin + margin flag
// ============================================================
__device__ __forceinline__ void prefetchB(uint32_t sb, int tid, int nt) {
    int s = nt & 1;
    int row = tid >> 3;                 // 0..31
    int c0  = (tid & 7) * 4;            // 16B-chunk base, 0..28
    const char* srcH = (const char*)g_eh + ((size_t)nt * 32 + row) * 512 + (size_t)c0 * 16;
    const char* srcL = (const char*)g_el + ((size_t)nt * 32 + row) * 512 + (size_t)c0 * 16;
    uint32_t dH = sb + SM_BH + (uint32_t)s * 16896u + (uint32_t)row * ROWSTR + (uint32_t)c0 * 16;
    uint32_t dL = sb + SM_BL + (uint32_t)s * 16896u + (uint32_t)row * ROWSTR + (uint32_t)c0 * 16;
    #pragma unroll
    for (int j = 0; j < 4; j++) {
        cpa16(dH + j * 16, srcH + j * 16);
        cpa16(dL + j * 16, srcL + j * 16);
    }
    if (tid < 8) cpa16(sb + SM_EN + (uint32_t)s * 128 + tid * 16,
                       (const char*)g_eN + (size_t)nt * 128 + tid * 16);
}

__global__ __launch_bounds__(256, 1)
void k_mma(const float* __restrict__ z) {
    extern __shared__ char smraw[];
    const uint32_t sb = smem_u32(smraw);
    const int tid  = threadIdx.x;
    const int lane = tid & 31;
    const int wid  = tid >> 5;
    const int mw   = wid >> 1;          // 0..3  (M-warp)
    const int nw   = wid & 1;           // 0..1  (N-warp)
    const int gid  = lane >> 2;
    const int tig  = lane & 3;
    const int row0 = blockIdx.x * 128;

    // prefetch stage 0 (all threads)
    prefetchB(sb, tid, 0);
    asm volatile("cp.async.commit_group;" ::: "memory");

    // ---- prologue: convert z rows to bf16 hi/lo in smem, exact zn ----
    if (tid < 128) {
        const float4* zr4 = (const float4*)(z + (size_t)(row0 + tid) * E_DIM);
        uint32_t* ahp = (uint32_t*)(smraw + SM_AH + (uint32_t)tid * ROWSTR);
        uint32_t* alp = (uint32_t*)(smraw + SM_AL + (uint32_t)tid * ROWSTR);
        float zn = 0.0f;
        #pragma unroll 4
        for (int i = 0; i < 64; i++) {
            float4 v = zr4[i];
            zn = __fadd_rn(zn, __fmul_rn(v.x, v.x));
            zn = __fadd_rn(zn, __fmul_rn(v.y, v.y));
            zn = __fadd_rn(zn, __fmul_rn(v.z, v.z));
            zn = __fadd_rn(zn, __fmul_rn(v.w, v.w));
            __nv_bfloat16 h0 = __float2bfloat16(v.x), h1 = __float2bfloat16(v.y);
            __nv_bfloat16 h2 = __float2bfloat16(v.z), h3 = __float2bfloat16(v.w);
            __nv_bfloat16 l0 = __float2bfloat16(__fsub_rn(v.x, __bfloat162float(h0)));
            __nv_bfloat16 l1 = __float2bfloat16(__fsub_rn(v.y, __bfloat162float(h1)));
            __nv_bfloat16 l2 = __float2bfloat16(__fsub_rn(v.z, __bfloat162float(h2)));
            __nv_bfloat16 l3 = __float2bfloat16(__fsub_rn(v.w, __bfloat162float(h3)));
            ahp[i * 2 + 0] = ((uint32_t)__bfloat16_as_ushort(h1) << 16) | __bfloat16_as_ushort(h0);
            ahp[i * 2 + 1] = ((uint32_t)__bfloat16_as_ushort(h3) << 16) | __bfloat16_as_ushort(h2);
            alp[i * 2 + 0] = ((uint32_t)__bfloat16_as_ushort(l1) << 16) | __bfloat16_as_ushort(l0);
            alp[i * 2 + 1] = ((uint32_t)__bfloat16_as_ushort(l3) << 16) | __bfloat16_as_ushort(l2);
        }
        *(float*)(smraw + SM_ZN + tid * 4) = zn;
        g_zn[row0 + tid] = zn;
    }
    __syncthreads();

    // ldmatrix base addresses
    uint32_t aH[2], aL[2], bH[2], bL[2];
    {
        uint32_t arow = (uint32_t)(lane & 15);
        uint32_t ab   = ((uint32_t)(lane >> 4) & 1) * 16;
        #pragma unroll
        for (int mt = 0; mt < 2; mt++) {
            uint32_t ro = (uint32_t)(mw * 32 + mt * 16) * ROWSTR + arow * ROWSTR + ab;
            aH[mt] = sb + SM_AH + ro;
            aL[mt] = sb + SM_AL + ro;
        }
        uint32_t brow = (uint32_t)(lane & 7);
        uint32_t bb   = ((uint32_t)(lane >> 3) & 1) * 16;
        #pragma unroll
        for (int nt2 = 0; nt2 < 2; nt2++) {
            uint32_t ro = (uint32_t)(nw * 16 + nt2 * 8) * ROWSTR + brow * ROWSTR + bb;
            bH[nt2] = sb + SM_BH + ro;
            bL[nt2] = sb + SM_BL + ro;
        }
    }

    float znv[4];
    #pragma unroll
    for (int sl = 0; sl < 4; sl++) {
        int r = mw * 32 + (sl >> 1) * 16 + (sl & 1) * 8 + gid;
        znv[sl] = *(const float*)(smraw + SM_ZN + r * 4);
    }

    float tb0[4], tb1[4];
    int   ti0[4], ti1[4];
    #pragma unroll
    for (int sl = 0; sl < 4; sl++) { tb0[sl] = 3.4e38f; tb1[sl] = 3.4e38f; ti0[sl] = 0; ti1[sl] = 0; }

    for (int nt = 0; nt < NSTG; nt++) {
        if (nt + 1 < NSTG) {
            prefetchB(sb, tid, nt + 1);
            asm volatile("cp.async.commit_group;" ::: "memory");
            asm volatile("cp.async.wait_group 1;" ::: "memory");
        } else {
            asm volatile("cp.async.wait_group 0;" ::: "memory");
        }
        __syncthreads();

        const uint32_t sof = (uint32_t)(nt & 1) * 16896u;
        float acc[2][2][4];
        #pragma unroll
        for (int mt = 0; mt < 2; mt++)
            #pragma unroll
            for (int n2 = 0; n2 < 2; n2++)
                #pragma unroll
                for (int q = 0; q < 4; q++) acc[mt][n2][q] = 0.0f;

        #pragma unroll
        for (int kk = 0; kk < 16; kk++) {
            uint32_t kb = (uint32_t)kk * 32;
            uint32_t ah0[4], ah1[4], al0[4], al1[4];
            uint32_t bh0[2], bh1[2], bl0[2], bl1[2];
            ldm4(ah0, aH[0] + kb); ldm4(ah1, aH[1] + kb);
            ldm4(al0, aL[0] + kb); ldm4(al1, aL[1] + kb);
            ldm2(bh0, bH[0] + sof + kb); ldm2(bh1, bH[1] + sof + kb);
            ldm2(bl0, bL[0] + sof + kb); ldm2(bl1, bL[1] + sof + kb);
            mma16816(acc[0][0], ah0, bh0); mma16816(acc[0][0], ah0, bl0); mma16816(acc[0][0], al0, bh0);
            mma16816(acc[0][1], ah0, bh1); mma16816(acc[0][1], ah0, bl1); mma16816(acc[0][1], al0, bh1);
            mma16816(acc[1][0], ah1, bh0); mma16816(acc[1][0], ah1, bl0); mma16816(acc[1][0], al1, bh0);
            mma16816(acc[1][1], ah1, bh1); mma16816(acc[1][1], ah1, bl1); mma16816(acc[1][1], al1, bh1);
        }

        // distances + per-slot top-2 (columns visited in ascending order)
        const float* eNs = (const float*)(smraw + SM_EN + (uint32_t)(nt & 1) * 128);
        #pragma unroll
        for (int n2 = 0; n2 < 2; n2++) {
            int colb = nt * 32 + nw * 16 + n2 * 8 + 2 * tig;
            float e0 = eNs[nw * 16 + n2 * 8 + 2 * tig];
            float e1 = eNs[nw * 16 + n2 * 8 + 2 * tig + 1];
            #pragma unroll
            for (int mt = 0; mt < 2; mt++)
                #pragma unroll
                for (int hh = 0; hh < 2; hh++) {
                    int sl = mt * 2 + hh;
                    float d0 = __fmaf_rn(-2.0f, acc[mt][n2][hh * 2 + 0], znv[sl] + e0);
                    float d1 = __fmaf_rn(-2.0f, acc[mt][n2][hh * 2 + 1], znv[sl] + e1);
                    if (d0 < tb1[sl]) {
                        if (d0 < tb0[sl]) { tb1[sl]=tb0[sl]; ti1[sl]=ti0[sl]; tb0[sl]=d0; ti0[sl]=colb; }
                        else              { tb1[sl]=d0; ti1[sl]=colb; }
                    }
                    if (d1 < tb1[sl]) {
                        if (d1 < tb0[sl]) { tb1[sl]=tb0[sl]; ti1[sl]=ti0[sl]; tb0[sl]=d1; ti0[sl]=colb+1; }
                        else              { tb1[sl]=d1; ti1[sl]=colb+1; }
                    }
                }
        }
        __syncthreads();
    }

    // ---- candidate table in smem (reuse A region) ----
    float* tD = (float*)smraw;           // [128][16]
    int*   tI = (int*)(smraw + 8192);    // [128][16]
    #pragma unroll
    for (int sl = 0; sl < 4; sl++) {
        int r = mw * 32 + (sl >> 1) * 16 + (sl & 1) * 8 + gid;
        int owner = nw * 4 + tig;        // 0..7
        tD[r * 16 + owner * 2 + 0] = tb0[sl];
        tI[r * 16 + owner * 2 + 0] = ti0[sl];
        tD[r * 16 + owner * 2 + 1] = tb1[sl];
        tI[r * 16 + owner * 2 + 1] = ti1[sl];
    }
    __syncthreads();

    if (tid < 128) {
        float b0 = 3.4e38f, b1 = 3.4e38f;
        int   i0 = 0x7FFFFFFF, i1 = 0x7FFFFFFF;
        #pragma unroll
        for (int q = 0; q < 16; q++) {
            float d = tD[tid * 16 + q];
            int   c = tI[tid * 16 + q];
            if (d < b0 || (d == b0 && c < i0)) { b1 = b0; i1 = i0; b0 = d; i0 = c; }
            else if (d < b1 || (d == b1 && c < i1)) { b1 = d; i1 = c; }
        }
        int r = row0 + tid;
        g_idxi[r] = i0;
        if (__fsub_rn(b1, b0) < TH_MARGIN) {
            int u = atomicAdd(&g_ucount, 1);
            g_urows[u] = r;
            #pragma unroll
            for (int q = 0; q < 16; q++) g_ucand[u * 16 + q] = tI[tid * 16 + q];
        }
    }
}

// ============================================================
// K4: exact rescore of flagged rows (R0-identical numerics), 16 candidates
// ============================================================
__global__ void k_rescore(const float* __restrict__ z, const float* __restrict__ emb) {
    int t = blockIdx.x * blockDim.x + threadIdx.x;
    if (t >= g_ucount) return;
    int r = g_urows[t];
    const float* zr = z + (size_t)r * E_DIM;
    float zn = g_zn[r];
    float bd = 3.4e38f;
    int   bi = 0x7FFFFFFF;
    #pragma unroll 1
    for (int q = 0; q < 16; q++) {
        int c = g_ucand[t * 16 + q];
        const float* er = emb + (size_t)c * E_DIM;
        float acc = 0.0f;
        #pragma unroll 8
        for (int k = 0; k < E_DIM; k++) acc = __fmaf_rn(zr[k], er[k], acc);
        float d = __fsub_rn(__fadd_rn(zn, g_eN[c]), __fmul_rn(2.0f, acc));
        if (d < bd || (d == bd && c < bi)) { bd = d; bi = c; }
    }
    g_idxi[r] = bi;
}

// ============================================================
// K5: epilogue — z_q/straight-through, loss partials, bins/dw atomics
// ============================================================
__global__ __launch_bounds__(256)
void k_epi(const float* __restrict__ z, const float* __restrict__ emb,
           float* __restrict__ out_zq, float* __restrict__ out_idx) {
    __shared__ float sl[256];
    int tid = threadIdx.x;
    int row0 = blockIdx.x * 128;
    int r = row0 + (tid >> 1);
    int h = tid & 1;
    int bi = g_idxi[r];
    if (h == 0) { out_idx[r] = (float)bi; atomicAdd(&g_bins[bi], 1.0f); }
    const float4* zr = (const float4*)(z + (size_t)r * E_DIM + h * 128);
    const float4* er = (const float4*)(emb + (size_t)bi * E_DIM + h * 128);
    float4* oq = (float4*)(out_zq + (size_t)r * E_DIM + h * 128);
    float* dw = g_dw + (size_t)bi * E_DIM + h * 128;
    float ls = 0.0f;
    #pragma unroll 4
    for (int d4 = 0; d4 < 32; d4++) {
        float4 zv = zr[d4];
        float4 ev = er[d4];
        float4 o;
        o.x = __fadd_rn(zv.x, __fsub_rn(ev.x, zv.x));
        o.y = __fadd_rn(zv.y, __fsub_rn(ev.y, zv.y));
        o.z = __fadd_rn(zv.z, __fsub_rn(ev.z, zv.z));
        o.w = __fadd_rn(zv.w, __fsub_rn(ev.w, zv.w));
        oq[d4] = o;
        float dx = __fsub_rn(zv.x, ev.x);
        float dy = __fsub_rn(zv.y, ev.y);
        float dz = __fsub_rn(zv.z, ev.z);
        float dwv = __fsub_rn(zv.w, ev.w);
        ls = __fadd_rn(ls, __fmul_rn(dx, dx));
        ls = __fadd_rn(ls, __fmul_rn(dy, dy));
        ls = __fadd_rn(ls, __fmul_rn(dz, dz));
        ls = __fadd_rn(ls, __fmul_rn(dwv, dwv));
        atomicAdd(dw + d4 * 4 + 0, zv.x);
        atomicAdd(dw + d4 * 4 + 1, zv.y);
        atomicAdd(dw + d4 * 4 + 2, zv.z);
        atomicAdd(dw + d4 * 4 + 3, zv.w);
    }
    sl[tid] = ls;
    __syncthreads();
    for (int s = 128; s > 0; s >>= 1) {
        if (tid < s) sl[tid] += sl[tid + s];
        __syncthreads();
    }
    if (tid == 0) atomicAdd(&g_loss, sl[0]);
}

// ============================================================
// K6: finalize new_embeddings + loss
// ============================================================
__global__ void k_final(float* __restrict__ out_nemb, float* __restrict__ out_loss) {
    int gid = blockIdx.x * blockDim.x + threadIdx.x;
    if (gid == 0) {
        float mean = __fdiv_rn(g_loss, 8388608.0f);
        out_loss[0] = __fmul_rn(0.25f, mean);
    }
    if (gid < N_E * E_DIM) {
        int k = gid >> 8;
        float b = g_bins[k];
        float t1 = __fadd_rn(b, 1e-5f);
        float cl = __fmul_rn(__fdiv_rn(t1, 32768.08192f), 32768.0f);
        out_nemb[gid] = __fdiv_rn(g_dw[gid], cl);
    }
}

// ============================================================
extern "C" void kernel_launch(void* const* d_in, const int* in_sizes, int n_in,
                              void* d_out, int out_size) {
    const float* z   = (const float*)d_in[0];
    const float* emb = (const float*)d_in[1];
    float* out = (float*)d_out;

    cudaFuncSetAttribute(k_mma, cudaFuncAttributeMaxDynamicSharedMemorySize, SM_DYN);

    k_init<<<8192, 256>>>(emb);
    k_prep<<<8192, 256>>>(emb);
    k_mma<<<N_TOK / 128, 256, SM_DYN>>>(z);
    k_rescore<<<128, 256>>>(z, emb);
    k_epi<<<N_TOK / 128, 256>>>(z, emb, out + OFF_ZQ, out + OFF_IDX);
    k_final<<<8192, 256>>>(out + OFF_NEMB, out + OFF_LOSS);
}

// round 9
// speedup vs baseline: 2.1563x; 1.5024x over previous
#include <cuda_runtime.h>
#include <cuda_fp16.h>
#include <cstdint>

#define N_E    8192
#define E_DIM  256
#define N_TOK  32768

#define OFF_ZQ   0
#define OFF_IDX  8388608
#define OFF_LOSS 8421376
#define OFF_NEMB 8421377

#define TH_MARGIN 4.0e-3f
#define BM     256
#define BN     64
#define NSTG   128               // 8192 / 64
#define ROWSTR 528u              // padded fp16 row stride bytes (256*2 + 16)

// dynamic smem layout (bytes)
#define SM_A   0u                // 256 x 528 = 135168
#define SM_B   135168u           // 2 stages x 64 x 528 = 67584
#define SM_EN  202752u           // 2 stages x 256B
#define SM_ZN  203264u           // 256 x 4B
#define SM_DYN 204800

// ---- device scratch (no allocations allowed) ----
__device__ float g_bins[N_E];
__device__ float g_dw[N_E * E_DIM];
__device__ float g_eN[N_E];
__device__ float g_loss;
__device__ int   g_ucount;
__device__ int   g_idxi[N_TOK];
__device__ float g_zn[N_TOK];
__device__ int   g_urows[N_TOK];
__device__ int   g_ucand[N_TOK * 16];
__device__ __half g_eh[N_E * E_DIM];

// ---------------- PTX helpers ----------------
__device__ __forceinline__ uint32_t smem_u32(const void* p) {
    uint32_t a;
    asm("{ .reg .u64 t; cvta.to.shared.u64 t, %1; cvt.u32.u64 %0, t; }" : "=r"(a) : "l"(p));
    return a;
}
__device__ __forceinline__ void cpa16(uint32_t dst, const void* src) {
    asm volatile("cp.async.cg.shared.global [%0], [%1], 16;" :: "r"(dst), "l"(src) : "memory");
}
__device__ __forceinline__ void ldm4(uint32_t* r, uint32_t a) {
    asm volatile("ldmatrix.sync.aligned.m8n8.x4.shared.b16 {%0,%1,%2,%3}, [%4];"
                 : "=r"(r[0]), "=r"(r[1]), "=r"(r[2]), "=r"(r[3]) : "r"(a));
}
__device__ __forceinline__ void ldm2(uint32_t* r, uint32_t a) {
    asm volatile("ldmatrix.sync.aligned.m8n8.x2.shared.b16 {%0,%1}, [%2];"
                 : "=r"(r[0]), "=r"(r[1]) : "r"(a));
}
__device__ __forceinline__ void mma16816(float* c, const uint32_t* a, const uint32_t* b) {
    asm volatile(
        "mma.sync.aligned.m16n8k16.row.col.f32.f16.f16.f32 "
        "{%0,%1,%2,%3}, {%4,%5,%6,%7}, {%8,%9}, {%0,%1,%2,%3};"
        : "+f"(c[0]), "+f"(c[1]), "+f"(c[2]), "+f"(c[3])
        : "r"(a[0]), "r"(a[1]), "r"(a[2]), "r"(a[3]), "r"(b[0]), "r"(b[1]));
}

// ============================================================
// K1: zero scratch + ||e||^2 (exact sequential, matches reference rounding)
// ============================================================
__global__ void k_init(const float* __restrict__ emb) {
    int gid = blockIdx.x * blockDim.x + threadIdx.x;
    if (gid < N_E * E_DIM) g_dw[gid] = 0.0f;
    if (gid < N_E) {
        g_bins[gid] = 0.0f;
        const float* e = emb + (size_t)gid * E_DIM;
        float s = 0.0f;
        #pragma unroll 8
        for (int k = 0; k < E_DIM; k++) s = __fadd_rn(s, __fmul_rn(e[k], e[k]));
        g_eN[gid] = s;
    }
    if (gid == 0) { g_loss = 0.0f; g_ucount = 0; }
}

// ============================================================
// K2: fp16 image of embeddings (row-major)
// ============================================================
__global__ void k_prep(const float* __restrict__ emb) {
    int gid = blockIdx.x * blockDim.x + threadIdx.x;   // over N_E*E_DIM
    g_eh[gid] = __float2half_rn(emb[gid]);
}

// ============================================================
// K3: fp16 mma.sync distance GEMM (single product) + top-2 + margin flag
//   CTA: 256 z-rows x all 8192 codes; 8 warps as 4M x 2N, warp tile 64x32
// ============================================================
__device__ __forceinline__ void prefetchB(uint32_t sb, int tid, int nt) {
    int s = nt & 1;
    int row = tid >> 2;                  // 0..63
    int q   = tid & 3;                   // 128B quarter
    const char* src = (const char*)g_eh + ((size_t)nt * BN + row) * 512 + (size_t)q * 128;
    uint32_t dst = sb + SM_B + (uint32_t)s * 33792u + (uint32_t)row * ROWSTR + (uint32_t)q * 128;
    #pragma unroll
    for (int j = 0; j < 8; j++) cpa16(dst + j * 16, src + j * 16);
    if (tid < 16) cpa16(sb + SM_EN + (uint32_t)s * 256 + tid * 16,
                        (const char*)g_eN + (size_t)nt * 256 + tid * 16);
}

__global__ __launch_bounds__(256, 1)
void k_mma(const float* __restrict__ z) {
    extern __shared__ char smraw[];
    const uint32_t sb = smem_u32(smraw);
    const int tid  = threadIdx.x;
    const int lane = tid & 31;
    const int wid  = tid >> 5;
    const int mw   = wid >> 1;           // 0..3
    const int nw   = wid & 1;            // 0..1
    const int gid  = lane >> 2;
    const int tig  = lane & 3;
    const int row0 = blockIdx.x * BM;

    prefetchB(sb, tid, 0);
    asm volatile("cp.async.commit_group;" ::: "memory");

    // ---- prologue: z rows -> fp16 in smem, exact zn (reference rounding) ----
    {
        const float4* zr4 = (const float4*)(z + (size_t)(row0 + tid) * E_DIM);
        uint32_t* ap = (uint32_t*)(smraw + SM_A + (uint32_t)tid * ROWSTR);
        float zn = 0.0f;
        #pragma unroll 4
        for (int i = 0; i < 64; i++) {
            float4 v = zr4[i];
            zn = __fadd_rn(zn, __fmul_rn(v.x, v.x));
            zn = __fadd_rn(zn, __fmul_rn(v.y, v.y));
            zn = __fadd_rn(zn, __fmul_rn(v.z, v.z));
            zn = __fadd_rn(zn, __fmul_rn(v.w, v.w));
            __half h0 = __float2half_rn(v.x), h1 = __float2half_rn(v.y);
            __half h2 = __float2half_rn(v.z), h3 = __float2half_rn(v.w);
            ap[i * 2 + 0] = ((uint32_t)__half_as_ushort(h1) << 16) | __half_as_ushort(h0);
            ap[i * 2 + 1] = ((uint32_t)__half_as_ushort(h3) << 16) | __half_as_ushort(h2);
        }
        *(float*)(smraw + SM_ZN + tid * 4) = zn;
        g_zn[row0 + tid] = zn;
    }
    __syncthreads();

    // ldmatrix base addresses
    uint32_t aA[4], bA[4];
    {
        uint32_t arow = (uint32_t)(lane & 15);
        uint32_t ab   = ((uint32_t)(lane >> 4) & 1) * 16;
        #pragma unroll
        for (int mt = 0; mt < 4; mt++)
            aA[mt] = sb + SM_A + ((uint32_t)(mw * 64 + mt * 16) + arow) * ROWSTR + ab;
        uint32_t brow = (uint32_t)(lane & 7);
        uint32_t bb   = ((uint32_t)(lane >> 3) & 1) * 16;
        #pragma unroll
        for (int n2 = 0; n2 < 4; n2++)
            bA[n2] = sb + SM_B + ((uint32_t)(nw * 32 + n2 * 8) + brow) * ROWSTR + bb;
    }

    float znv[8];
    #pragma unroll
    for (int sl = 0; sl < 8; sl++) {
        int r = mw * 64 + (sl >> 1) * 16 + (sl & 1) * 8 + gid;
        znv[sl] = *(const float*)(smraw + SM_ZN + r * 4);
    }

    float tb0[8], tb1[8];
    int   ti0[8], ti1[8];
    #pragma unroll
    for (int sl = 0; sl < 8; sl++) { tb0[sl] = 3.4e38f; tb1[sl] = 3.4e38f; ti0[sl] = 0; ti1[sl] = 0; }

    for (int nt = 0; nt < NSTG; nt++) {
        if (nt + 1 < NSTG) {
            prefetchB(sb, tid, nt + 1);
            asm volatile("cp.async.commit_group;" ::: "memory");
            asm volatile("cp.async.wait_group 1;" ::: "memory");
        } else {
            asm volatile("cp.async.wait_group 0;" ::: "memory");
        }
        __syncthreads();

        const uint32_t sof = (uint32_t)(nt & 1) * 33792u;
        float acc[4][4][4];
        #pragma unroll
        for (int mt = 0; mt < 4; mt++)
            #pragma unroll
            for (int n2 = 0; n2 < 4; n2++)
                #pragma unroll
                for (int q = 0; q < 4; q++) acc[mt][n2][q] = 0.0f;

        #pragma unroll
        for (int kk = 0; kk < 16; kk++) {
            uint32_t kb = (uint32_t)kk * 32;
            uint32_t af[4][4], bf[4][2];
            #pragma unroll
            for (int mt = 0; mt < 4; mt++) ldm4(af[mt], aA[mt] + kb);
            #pragma unroll
            for (int n2 = 0; n2 < 4; n2++) ldm2(bf[n2], bA[n2] + sof + kb);
            #pragma unroll
            for (int mt = 0; mt < 4; mt++)
                #pragma unroll
                for (int n2 = 0; n2 < 4; n2++)
                    mma16816(acc[mt][n2], af[mt], bf[n2]);
        }

        // distances + per-slot top-2 (columns ascending)
        const float* eNs = (const float*)(smraw + SM_EN + (uint32_t)(nt & 1) * 256);
        #pragma unroll
        for (int n2 = 0; n2 < 4; n2++) {
            int colb = nt * BN + nw * 32 + n2 * 8 + 2 * tig;
            float e0 = eNs[nw * 32 + n2 * 8 + 2 * tig];
            float e1 = eNs[nw * 32 + n2 * 8 + 2 * tig + 1];
            #pragma unroll
            for (int mt = 0; mt < 4; mt++)
                #pragma unroll
                for (int hh = 0; hh < 2; hh++) {
                    int sl = mt * 2 + hh;
                    float d0 = __fmaf_rn(-2.0f, acc[mt][n2][hh * 2 + 0], znv[sl] + e0);
                    float d1 = __fmaf_rn(-2.0f, acc[mt][n2][hh * 2 + 1], znv[sl] + e1);
                    if (d0 < tb1[sl]) {
                        if (d0 < tb0[sl]) { tb1[sl]=tb0[sl]; ti1[sl]=ti0[sl]; tb0[sl]=d0; ti0[sl]=colb; }
                        else              { tb1[sl]=d0; ti1[sl]=colb; }
                    }
                    if (d1 < tb1[sl]) {
                        if (d1 < tb0[sl]) { tb1[sl]=tb0[sl]; ti1[sl]=ti0[sl]; tb0[sl]=d1; ti0[sl]=colb+1; }
                        else              { tb1[sl]=d1; ti1[sl]=colb+1; }
                    }
                }
        }
        __syncthreads();
    }

    // ---- candidate table in smem (reuse A region) ----
    float* tD = (float*)smraw;            // [256][16]
    int*   tI = (int*)(smraw + 16384);    // [256][16]
    #pragma unroll
    for (int sl = 0; sl < 8; sl++) {
        int r = mw * 64 + (sl >> 1) * 16 + (sl & 1) * 8 + gid;
        int owner = nw * 4 + tig;         // 0..7
        tD[r * 16 + owner * 2 + 0] = tb0[sl];
        tI[r * 16 + owner * 2 + 0] = ti0[sl];
        tD[r * 16 + owner * 2 + 1] = tb1[sl];
        tI[r * 16 + owner * 2 + 1] = ti1[sl];
    }
    __syncthreads();

    {
        float b0 = 3.4e38f, b1 = 3.4e38f;
        int   i0 = 0x7FFFFFFF, i1 = 0x7FFFFFFF;
        #pragma unroll
        for (int q = 0; q < 16; q++) {
            float d = tD[tid * 16 + q];
            int   c = tI[tid * 16 + q];
            if (d < b0 || (d == b0 && c < i0)) { b1 = b0; i1 = i0; b0 = d; i0 = c; }
            else if (d < b1 || (d == b1 && c < i1)) { b1 = d; i1 = c; }
        }
        int r = row0 + tid;
        g_idxi[r] = i0;
        if (__fsub_rn(b1, b0) < TH_MARGIN) {
            int u = atomicAdd(&g_ucount, 1);
            g_urows[u] = r;
            #pragma unroll
            for (int q = 0; q < 16; q++) g_ucand[u * 16 + q] = tI[tid * 16 + q];
        }
    }
}

// ============================================================
// K4: exact rescore of flagged rows (R0-identical numerics), 16 candidates
// ============================================================
__global__ void k_rescore(const float* __restrict__ z, const float* __restrict__ emb) {
    int t = blockIdx.x * blockDim.x + threadIdx.x;
    if (t >= g_ucount) return;
    int r = g_urows[t];
    const float* zr = z + (size_t)r * E_DIM;
    float zn = g_zn[r];
    float bd = 3.4e38f;
    int   bi = 0x7FFFFFFF;
    #pragma unroll 1
    for (int q = 0; q < 16; q++) {
        int c = g_ucand[t * 16 + q];
        const float* er = emb + (size_t)c * E_DIM;
        float acc = 0.0f;
        #pragma unroll 8
        for (int k = 0; k < E_DIM; k++) acc = __fmaf_rn(zr[k], er[k], acc);
        float d = __fsub_rn(__fadd_rn(zn, g_eN[c]), __fmul_rn(2.0f, acc));
        if (d < bd || (d == bd && c < bi)) { bd = d; bi = c; }
    }
    g_idxi[r] = bi;
}

// ============================================================
// K5: epilogue — z_q/straight-through, loss partials, bins/dw atomics
// ============================================================
__global__ __launch_bounds__(256)
void k_epi(const float* __restrict__ z, const float* __restrict__ emb,
           float* __restrict__ out_zq, float* __restrict__ out_idx) {
    __shared__ float sl[256];
    int tid = threadIdx.x;
    int row0 = blockIdx.x * 128;
    int r = row0 + (tid >> 1);
    int h = tid & 1;
    int bi = g_idxi[r];
    if (h == 0) { out_idx[r] = (float)bi; atomicAdd(&g_bins[bi], 1.0f); }
    const float4* zr = (const float4*)(z + (size_t)r * E_DIM + h * 128);
    const float4* er = (const float4*)(emb + (size_t)bi * E_DIM + h * 128);
    float4* oq = (float4*)(out_zq + (size_t)r * E_DIM + h * 128);
    float* dw = g_dw + (size_t)bi * E_DIM + h * 128;
    float ls = 0.0f;
    #pragma unroll 4
    for (int d4 = 0; d4 < 32; d4++) {
        float4 zv = zr[d4];
        float4 ev = er[d4];
        float4 o;
        o.x = __fadd_rn(zv.x, __fsub_rn(ev.x, zv.x));
        o.y = __fadd_rn(zv.y, __fsub_rn(ev.y, zv.y));
        o.z = __fadd_rn(zv.z, __fsub_rn(ev.z, zv.z));
        o.w = __fadd_rn(zv.w, __fsub_rn(ev.w, zv.w));
        oq[d4] = o;
        float dx = __fsub_rn(zv.x, ev.x);
        float dy = __fsub_rn(zv.y, ev.y);
        float dz = __fsub_rn(zv.z, ev.z);
        float dwv = __fsub_rn(zv.w, ev.w);
        ls = __fadd_rn(ls, __fmul_rn(dx, dx));
        ls = __fadd_rn(ls, __fmul_rn(dy, dy));
        ls = __fadd_rn(ls, __fmul_rn(dz, dz));
        ls = __fadd_rn(ls, __fmul_rn(dwv, dwv));
        atomicAdd(dw + d4 * 4 + 0, zv.x);
        atomicAdd(dw + d4 * 4 + 1, zv.y);
        atomicAdd(dw + d4 * 4 + 2, zv.z);
        atomicAdd(dw + d4 * 4 + 3, zv.w);
    }
    sl[tid] = ls;
    __syncthreads();
    for (int s = 128; s > 0; s >>= 1) {
        if (tid < s) sl[tid] += sl[tid + s];
        __syncthreads();
    }
    if (tid == 0) atomicAdd(&g_loss, sl[0]);
}

// ============================================================
// K6: finalize new_embeddings + loss
// ============================================================
__global__ void k_final(float* __restrict__ out_nemb, float* __restrict__ out_loss) {
    int gid = blockIdx.x * blockDim.x + threadIdx.x;
    if (gid == 0) {
        float mean = __fdiv_rn(g_loss, 8388608.0f);
        out_loss[0] = __fmul_rn(0.25f, mean);
    }
    if (gid < N_E * E_DIM) {
        int k = gid >> 8;
        float b = g_bins[k];
        float t1 = __fadd_rn(b, 1e-5f);
        float cl = __fmul_rn(__fdiv_rn(t1, 32768.08192f), 32768.0f);
        out_nemb[gid] = __fdiv_rn(g_dw[gid], cl);
    }
}

// ============================================================
extern "C" void kernel_launch(void* const* d_in, const int* in_sizes, int n_in,
                              void* d_out, int out_size) {
    const float* z   = (const float*)d_in[0];
    const float* emb = (const float*)d_in[1];
    float* out = (float*)d_out;

    cudaFuncSetAttribute(k_mma, cudaFuncAttributeMaxDynamicSharedMemorySize, SM_DYN);

    k_init<<<8192, 256>>>(emb);
    k_prep<<<8192, 256>>>(emb);
    k_mma<<<N_TOK / BM, 256, SM_DYN>>>(z);
    k_rescore<<<128, 256>>>(z, emb);
    k_epi<<<N_TOK / 128, 256>>>(z, emb, out + OFF_ZQ, out + OFF_IDX);
    k_final<<<8192, 256>>>(out + OFF_NEMB, out + OFF_LOSS);
}

// round 10
// speedup vs baseline: 2.1709x; 1.0068x over previous
#include <cuda_runtime.h>
#include <cuda_fp16.h>
#include <cstdint>

#define N_E    8192
#define E_DIM  256
#define N_TOK  32768

#define OFF_ZQ   0
#define OFF_IDX  8388608
#define OFF_LOSS 8421376
#define OFF_NEMB 8421377

#define TH_MARGIN 4.0e-3f
#define BM     256
#define BN     64
#define NSTG   128               // 8192 / 64
#define ROWSTR 528u              // padded fp16 row stride bytes (256*2 + 16)

// dynamic smem layout (bytes)
#define SM_A   0u                // 256 x 528 = 135168
#define SM_B   135168u           // 2 stages x 64 x 528 = 67584
#define SM_EN  202752u           // 2 stages x 256B
#define SM_ZN  203264u           // 256 x 4B
#define SM_DYN 204800

// ---- device scratch (no allocations allowed) ----
__device__ float g_bins[N_E];
__device__ float g_dw[N_E * E_DIM];
__device__ float g_eN[N_E];
__device__ float g_loss;
__device__ int   g_ucount;
__device__ int   g_idxi[N_TOK];
__device__ float g_zn[N_TOK];
__device__ int   g_urows[N_TOK];
__device__ int   g_ucand[N_TOK * 16];
__device__ __half g_eh[N_E * E_DIM];

// ---------------- PTX helpers ----------------
__device__ __forceinline__ uint32_t smem_u32(const void* p) {
    uint32_t a;
    asm("{ .reg .u64 t; cvta.to.shared.u64 t, %1; cvt.u32.u64 %0, t; }" : "=r"(a) : "l"(p));
    return a;
}
__device__ __forceinline__ void cpa16(uint32_t dst, const void* src) {
    asm volatile("cp.async.cg.shared.global [%0], [%1], 16;" :: "r"(dst), "l"(src) : "memory");
}
__device__ __forceinline__ void ldm4(uint32_t* r, uint32_t a) {
    asm volatile("ldmatrix.sync.aligned.m8n8.x4.shared.b16 {%0,%1,%2,%3}, [%4];"
                 : "=r"(r[0]), "=r"(r[1]), "=r"(r[2]), "=r"(r[3]) : "r"(a));
}
__device__ __forceinline__ void mma16816(float* c, const uint32_t* a, const uint32_t* b) {
    asm volatile(
        "mma.sync.aligned.m16n8k16.row.col.f32.f16.f16.f32 "
        "{%0,%1,%2,%3}, {%4,%5,%6,%7}, {%8,%9}, {%0,%1,%2,%3};"
        : "+f"(c[0]), "+f"(c[1]), "+f"(c[2]), "+f"(c[3])
        : "r"(a[0]), "r"(a[1]), "r"(a[2]), "r"(a[3]), "r"(b[0]), "r"(b[1]));
}

// ============================================================
// K1: zero scratch + ||e||^2 (exact sequential, matches reference rounding)
// ============================================================
__global__ void k_init(const float* __restrict__ emb) {
    int gid = blockIdx.x * blockDim.x + threadIdx.x;
    if (gid < N_E * E_DIM) g_dw[gid] = 0.0f;
    if (gid < N_E) {
        g_bins[gid] = 0.0f;
        const float* e = emb + (size_t)gid * E_DIM;
        float s = 0.0f;
        #pragma unroll 8
        for (int k = 0; k < E_DIM; k++) s = __fadd_rn(s, __fmul_rn(e[k], e[k]));
        g_eN[gid] = s;
    }
    if (gid == 0) { g_loss = 0.0f; g_ucount = 0; }
}

// ============================================================
// K2: fp16 image of embeddings (row-major)
// ============================================================
__global__ void k_prep(const float* __restrict__ emb) {
    int gid = blockIdx.x * blockDim.x + threadIdx.x;   // over N_E*E_DIM
    g_eh[gid] = __float2half_rn(emb[gid]);
}

// ============================================================
// K3: fp16 mma.sync distance GEMM + top-2 + margin flag
//   CTA: 256 z-rows x all 8192 codes; 512 thr / 16 warps as 8M x 2N,
//   warp tile 32x32 (4 warps per SMSP for latency hiding)
// ============================================================
__device__ __forceinline__ void prefetchB(uint32_t sb, int tid, int nt) {
    int s = nt & 1;
    int row = tid >> 3;                  // 0..63
    int q   = tid & 7;                   // 64B eighth
    const char* src = (const char*)g_eh + ((size_t)nt * BN + row) * 512 + (size_t)q * 64;
    uint32_t dst = sb + SM_B + (uint32_t)s * 33792u + (uint32_t)row * ROWSTR + (uint32_t)q * 64;
    #pragma unroll
    for (int j = 0; j < 4; j++) cpa16(dst + j * 16, src + j * 16);
    if (tid < 16) cpa16(sb + SM_EN + (uint32_t)s * 256 + tid * 16,
                        (const char*)g_eN + (size_t)nt * 256 + tid * 16);
}

__global__ __launch_bounds__(512, 1)
void k_mma(const float* __restrict__ z) {
    extern __shared__ char smraw[];
    const uint32_t sb = smem_u32(smraw);
    const int tid  = threadIdx.x;
    const int lane = tid & 31;
    const int wid  = tid >> 5;           // 0..15
    const int mw   = wid >> 1;           // 0..7  (M-warp, 32 rows each)
    const int nw   = wid & 1;            // 0..1  (N-warp, 32 cols each)
    const int gid  = lane >> 2;
    const int tig  = lane & 3;
    const int row0 = blockIdx.x * BM;

    prefetchB(sb, tid, 0);
    asm volatile("cp.async.commit_group;" ::: "memory");

    // ---- prologue: z rows -> fp16 in smem, exact zn (reference rounding) ----
    if (tid < BM) {
        const float4* zr4 = (const float4*)(z + (size_t)(row0 + tid) * E_DIM);
        uint32_t* ap = (uint32_t*)(smraw + SM_A + (uint32_t)tid * ROWSTR);
        float zn = 0.0f;
        #pragma unroll 4
        for (int i = 0; i < 64; i++) {
            float4 v = zr4[i];
            zn = __fadd_rn(zn, __fmul_rn(v.x, v.x));
            zn = __fadd_rn(zn, __fmul_rn(v.y, v.y));
            zn = __fadd_rn(zn, __fmul_rn(v.z, v.z));
            zn = __fadd_rn(zn, __fmul_rn(v.w, v.w));
            __half h0 = __float2half_rn(v.x), h1 = __float2half_rn(v.y);
            __half h2 = __float2half_rn(v.z), h3 = __float2half_rn(v.w);
            ap[i * 2 + 0] = ((uint32_t)__half_as_ushort(h1) << 16) | __half_as_ushort(h0);
            ap[i * 2 + 1] = ((uint32_t)__half_as_ushort(h3) << 16) | __half_as_ushort(h2);
        }
        *(float*)(smraw + SM_ZN + tid * 4) = zn;
        g_zn[row0 + tid] = zn;
    }
    __syncthreads();

    // ldmatrix base addresses
    uint32_t aA[2], bA[2];
    {
        uint32_t arow = (uint32_t)(lane & 15);
        uint32_t ab   = ((uint32_t)(lane >> 4) & 1) * 16;
        #pragma unroll
        for (int mt = 0; mt < 2; mt++)
            aA[mt] = sb + SM_A + ((uint32_t)(mw * 32 + mt * 16) + arow) * ROWSTR + ab;
        #pragma unroll
        for (int p = 0; p < 2; p++)
            bA[p] = sb + SM_B + ((uint32_t)(nw * 32 + p * 16) + arow) * ROWSTR + ab;
    }

    float znv[4];
    #pragma unroll
    for (int sl = 0; sl < 4; sl++) {
        int r = mw * 32 + (sl >> 1) * 16 + (sl & 1) * 8 + gid;
        znv[sl] = *(const float*)(smraw + SM_ZN + r * 4);
    }

    float tb0[4], tb1[4];
    int   ti0[4], ti1[4];
    #pragma unroll
    for (int sl = 0; sl < 4; sl++) { tb0[sl] = 3.4e38f; tb1[sl] = 3.4e38f; ti0[sl] = 0; ti1[sl] = 0; }

    for (int nt = 0; nt < NSTG; nt++) {
        if (nt + 1 < NSTG) {
            prefetchB(sb, tid, nt + 1);
            asm volatile("cp.async.commit_group;" ::: "memory");
            asm volatile("cp.async.wait_group 1;" ::: "memory");
        } else {
            asm volatile("cp.async.wait_group 0;" ::: "memory");
        }
        __syncthreads();

        const uint32_t sof = (uint32_t)(nt & 1) * 33792u;
        float acc[2][4][4];
        #pragma unroll
        for (int mt = 0; mt < 2; mt++)
            #pragma unroll
            for (int n2 = 0; n2 < 4; n2++)
                #pragma unroll
                for (int q = 0; q < 4; q++) acc[mt][n2][q] = 0.0f;

        #pragma unroll
        for (int kk = 0; kk < 16; kk++) {
            uint32_t kb = (uint32_t)kk * 32;
            uint32_t af[2][4], bw[2][4];
            ldm4(af[0], aA[0] + kb);
            ldm4(af[1], aA[1] + kb);
            ldm4(bw[0], bA[0] + sof + kb);   // n-tiles 0,1: frags {r0,r2},{r1,r3}
            ldm4(bw[1], bA[1] + sof + kb);   // n-tiles 2,3
            #pragma unroll
            for (int mt = 0; mt < 2; mt++)
                #pragma unroll
                for (int p = 0; p < 2; p++)
                    #pragma unroll
                    for (int q = 0; q < 2; q++) {
                        uint32_t bf[2] = { bw[p][q], bw[p][q + 2] };
                        mma16816(acc[mt][p * 2 + q], af[mt], bf);
                    }
        }

        // distances + per-slot top-2 (columns ascending)
        const float* eNs = (const float*)(smraw + SM_EN + (uint32_t)(nt & 1) * 256);
        #pragma unroll
        for (int n2 = 0; n2 < 4; n2++) {
            int colb = nt * BN + nw * 32 + n2 * 8 + 2 * tig;
            float e0 = eNs[nw * 32 + n2 * 8 + 2 * tig];
            float e1 = eNs[nw * 32 + n2 * 8 + 2 * tig + 1];
            #pragma unroll
            for (int mt = 0; mt < 2; mt++)
                #pragma unroll
                for (int hh = 0; hh < 2; hh++) {
                    int sl = mt * 2 + hh;
                    float d0 = __fmaf_rn(-2.0f, acc[mt][n2][hh * 2 + 0], znv[sl] + e0);
                    float d1 = __fmaf_rn(-2.0f, acc[mt][n2][hh * 2 + 1], znv[sl] + e1);
                    if (d0 < tb1[sl]) {
                        if (d0 < tb0[sl]) { tb1[sl]=tb0[sl]; ti1[sl]=ti0[sl]; tb0[sl]=d0; ti0[sl]=colb; }
                        else              { tb1[sl]=d0; ti1[sl]=colb; }
                    }
                    if (d1 < tb1[sl]) {
                        if (d1 < tb0[sl]) { tb1[sl]=tb0[sl]; ti1[sl]=ti0[sl]; tb0[sl]=d1; ti0[sl]=colb+1; }
                        else              { tb1[sl]=d1; ti1[sl]=colb+1; }
                    }
                }
        }
        __syncthreads();
    }

    // ---- candidate table in smem (reuse A region) ----
    float* tD = (float*)smraw;            // [256][16]
    int*   tI = (int*)(smraw + 16384);    // [256][16]
    #pragma unroll
    for (int sl = 0; sl < 4; sl++) {
        int r = mw * 32 + (sl >> 1) * 16 + (sl & 1) * 8 + gid;
        int owner = nw * 4 + tig;         // 0..7
        tD[r * 16 + owner * 2 + 0] = tb0[sl];
        tI[r * 16 + owner * 2 + 0] = ti0[sl];
        tD[r * 16 + owner * 2 + 1] = tb1[sl];
        tI[r * 16 + owner * 2 + 1] = ti1[sl];
    }
    __syncthreads();

    if (tid < BM) {
        float b0 = 3.4e38f, b1 = 3.4e38f;
        int   i0 = 0x7FFFFFFF, i1 = 0x7FFFFFFF;
        #pragma unroll
        for (int q = 0; q < 16; q++) {
            float d = tD[tid * 16 + q];
            int   c = tI[tid * 16 + q];
            if (d < b0 || (d == b0 && c < i0)) { b1 = b0; i1 = i0; b0 = d; i0 = c; }
            else if (d < b1 || (d == b1 && c < i1)) { b1 = d; i1 = c; }
        }
        int r = row0 + tid;
        g_idxi[r] = i0;
        if (__fsub_rn(b1, b0) < TH_MARGIN) {
            int u = atomicAdd(&g_ucount, 1);
            g_urows[u] = r;
            #pragma unroll
            for (int q = 0; q < 16; q++) g_ucand[u * 16 + q] = tI[tid * 16 + q];
        }
    }
}

// ============================================================
// K4: exact rescore of flagged rows (R0-identical numerics), 16 candidates
// ============================================================
__global__ void k_rescore(const float* __restrict__ z, const float* __restrict__ emb) {
    int t = blockIdx.x * blockDim.x + threadIdx.x;
    if (t >= g_ucount) return;
    int r = g_urows[t];
    const float* zr = z + (size_t)r * E_DIM;
    float zn = g_zn[r];
    float bd = 3.4e38f;
    int   bi = 0x7FFFFFFF;
    #pragma unroll 1
    for (int q = 0; q < 16; q++) {
        int c = g_ucand[t * 16 + q];
        const float* er = emb + (size_t)c * E_DIM;
        float acc = 0.0f;
        #pragma unroll 8
        for (int k = 0; k < E_DIM; k++) acc = __fmaf_rn(zr[k], er[k], acc);
        float d = __fsub_rn(__fadd_rn(zn, g_eN[c]), __fmul_rn(2.0f, acc));
        if (d < bd || (d == bd && c < bi)) { bd = d; bi = c; }
    }
    g_idxi[r] = bi;
}

// ============================================================
// K5: epilogue — z_q/straight-through, loss partials, bins/dw atomics
// ============================================================
__global__ __launch_bounds__(256)
void k_epi(const float* __restrict__ z, const float* __restrict__ emb,
           float* __restrict__ out_zq, float* __restrict__ out_idx) {
    __shared__ float sl[256];
    int tid = threadIdx.x;
    int row0 = blockIdx.x * 128;
    int r = row0 + (tid >> 1);
    int h = tid & 1;
    int bi = g_idxi[r];
    if (h == 0) { out_idx[r] = (float)bi; atomicAdd(&g_bins[bi], 1.0f); }
    const float4* zr = (const float4*)(z + (size_t)r * E_DIM + h * 128);
    const float4* er = (const float4*)(emb + (size_t)bi * E_DIM + h * 128);
    float4* oq = (float4*)(out_zq + (size_t)r * E_DIM + h * 128);
    float* dw = g_dw + (size_t)bi * E_DIM + h * 128;
    float ls = 0.0f;
    #pragma unroll 4
    for (int d4 = 0; d4 < 32; d4++) {
        float4 zv = zr[d4];
        float4 ev = er[d4];
        float4 o;
        o.x = __fadd_rn(zv.x, __fsub_rn(ev.x, zv.x));
        o.y = __fadd_rn(zv.y, __fsub_rn(ev.y, zv.y));
        o.z = __fadd_rn(zv.z, __fsub_rn(ev.z, zv.z));
        o.w = __fadd_rn(zv.w, __fsub_rn(ev.w, zv.w));
        oq[d4] = o;
        float dx = __fsub_rn(zv.x, ev.x);
        float dy = __fsub_rn(zv.y, ev.y);
        float dz = __fsub_rn(zv.z, ev.z);
        float dwv = __fsub_rn(zv.w, ev.w);
        ls = __fadd_rn(ls, __fmul_rn(dx, dx));
        ls = __fadd_rn(ls, __fmul_rn(dy, dy));
        ls = __fadd_rn(ls, __fmul_rn(dz, dz));
        ls = __fadd_rn(ls, __fmul_rn(dwv, dwv));
        atomicAdd(dw + d4 * 4 + 0, zv.x);
        atomicAdd(dw + d4 * 4 + 1, zv.y);
        atomicAdd(dw + d4 * 4 + 2, zv.z);
        atomicAdd(dw + d4 * 4 + 3, zv.w);
    }
    sl[tid] = ls;
    __syncthreads();
    for (int s = 128; s > 0; s >>= 1) {
        if (tid < s) sl[tid] += sl[tid + s];
        __syncthreads();
    }
    if (tid == 0) atomicAdd(&g_loss, sl[0]);
}

// ============================================================
// K6: finalize new_embeddings + loss
// ============================================================
__global__ void k_final(float* __restrict__ out_nemb, float* __restrict__ out_loss) {
    int gid = blockIdx.x * blockDim.x + threadIdx.x;
    if (gid == 0) {
        float mean = __fdiv_rn(g_loss, 8388608.0f);
        out_loss[0] = __fmul_rn(0.25f, mean);
    }
    if (gid < N_E * E_DIM) {
        int k = gid >> 8;
        float b = g_bins[k];
        float t1 = __fadd_rn(b, 1e-5f);
        float cl = __fmul_rn(__fdiv_rn(t1, 32768.08192f), 32768.0f);
        out_nemb[gid] = __fdiv_rn(g_dw[gid], cl);
    }
}

// ============================================================
extern "C" void kernel_launch(void* const* d_in, const int* in_sizes, int n_in,
                              void* d_out, int out_size) {
    const float* z   = (const float*)d_in[0];
    const float* emb = (const float*)d_in[1];
    float* out = (float*)d_out;

    cudaFuncSetAttribute(k_mma, cudaFuncAttributeMaxDynamicSharedMemorySize, SM_DYN);

    k_init<<<8192, 256>>>(emb);
    k_prep<<<8192, 256>>>(emb);
    k_mma<<<N_TOK / BM, 512, SM_DYN>>>(z);
    k_rescore<<<128, 256>>>(z, emb);
    k_epi<<<N_TOK / 128, 256>>>(z, emb, out + OFF_ZQ, out + OFF_IDX);
    k_final<<<8192, 256>>>(out + OFF_NEMB, out + OFF_LOSS);
}

// round 11
// speedup vs baseline: 2.1978x; 1.0124x over previous
#include <cuda_runtime.h>
#include <cuda_fp16.h>
#include <cstdint>

#define N_E    8192
#define E_DIM  256
#define N_TOK  32768

#define OFF_ZQ   0
#define OFF_IDX  8388608
#define OFF_LOSS 8421376
#define OFF_NEMB 8421377

#define TH_MARGIN 1.0e-2f
#define BM     256
#define BN     64
#define NSTG   128               // 8192 / 64
#define ROWSTR 528u              // padded fp16 row stride bytes (256*2 + 16)

// dynamic smem layout (bytes)
#define SM_A   0u                // 256 x 528 = 135168
#define SM_B   135168u           // 2 stages x 64 x 528 = 67584
#define SM_EN  202752u           // 2 stages x 256B
#define SM_ZN  203264u           // 256 x 4B
#define SM_DYN 204800

// ---- device scratch (no allocations allowed) ----
__device__ float g_bins[N_E];
__device__ float g_dw[N_E * E_DIM];
__device__ float g_eN[N_E];
__device__ float g_loss;
__device__ int   g_ucount;
__device__ int   g_idxi[N_TOK];
__device__ float g_zn[N_TOK];
__device__ int   g_urows[N_TOK];
__device__ int   g_ucand[N_TOK * 16];
__device__ __half g_eh[N_E * E_DIM];

// ---------------- PTX helpers ----------------
__device__ __forceinline__ uint32_t smem_u32(const void* p) {
    uint32_t a;
    asm("{ .reg .u64 t; cvta.to.shared.u64 t, %1; cvt.u32.u64 %0, t; }" : "=r"(a) : "l"(p));
    return a;
}
__device__ __forceinline__ void cpa16(uint32_t dst, const void* src) {
    asm volatile("cp.async.cg.shared.global [%0], [%1], 16;" :: "r"(dst), "l"(src) : "memory");
}
__device__ __forceinline__ void ldm4(uint32_t* r, uint32_t a) {
    asm volatile("ldmatrix.sync.aligned.m8n8.x4.shared.b16 {%0,%1,%2,%3}, [%4];"
                 : "=r"(r[0]), "=r"(r[1]), "=r"(r[2]), "=r"(r[3]) : "r"(a));
}
// fp16-accumulator HMMA: D(f16x2 x2) = A x B + C
__device__ __forceinline__ void mma16816h(uint32_t* c, const uint32_t* a, const uint32_t* b) {
    asm volatile(
        "mma.sync.aligned.m16n8k16.row.col.f16.f16.f16.f16 "
        "{%0,%1}, {%2,%3,%4,%5}, {%6,%7}, {%0,%1};"
        : "+r"(c[0]), "+r"(c[1])
        : "r"(a[0]), "r"(a[1]), "r"(a[2]), "r"(a[3]), "r"(b[0]), "r"(b[1]));
}

// ============================================================
// K1: zero scratch + ||e||^2 (exact sequential, matches reference rounding)
// ============================================================
__global__ void k_init(const float* __restrict__ emb) {
    int gid = blockIdx.x * blockDim.x + threadIdx.x;
    if (gid < N_E * E_DIM) g_dw[gid] = 0.0f;
    if (gid < N_E) {
        g_bins[gid] = 0.0f;
        const float* e = emb + (size_t)gid * E_DIM;
        float s = 0.0f;
        #pragma unroll 8
        for (int k = 0; k < E_DIM; k++) s = __fadd_rn(s, __fmul_rn(e[k], e[k]));
        g_eN[gid] = s;
    }
    if (gid == 0) { g_loss = 0.0f; g_ucount = 0; }
}

// ============================================================
// K2: fp16 image of embeddings (row-major)
// ============================================================
__global__ void k_prep(const float* __restrict__ emb) {
    int gid = blockIdx.x * blockDim.x + threadIdx.x;   // over N_E*E_DIM
    g_eh[gid] = __float2half_rn(emb[gid]);
}

// ============================================================
// K3: fp16 mma.sync (f16 acc) distance GEMM + top-2 + margin flag
//   CTA: 256 z-rows x all 8192 codes; 512 thr / 16 warps as 8M x 2N,
//   warp tile 32x32
// ============================================================
__device__ __forceinline__ void prefetchB(uint32_t sb, int tid, int nt) {
    int s = nt & 1;
    int row = tid >> 3;                  // 0..63
    int q   = tid & 7;                   // 64B eighth
    const char* src = (const char*)g_eh + ((size_t)nt * BN + row) * 512 + (size_t)q * 64;
    uint32_t dst = sb + SM_B + (uint32_t)s * 33792u + (uint32_t)row * ROWSTR + (uint32_t)q * 64;
    #pragma unroll
    for (int j = 0; j < 4; j++) cpa16(dst + j * 16, src + j * 16);
    if (tid < 16) cpa16(sb + SM_EN + (uint32_t)s * 256 + tid * 16,
                        (const char*)g_eN + (size_t)nt * 256 + tid * 16);
}

__global__ __launch_bounds__(512, 1)
void k_mma(const float* __restrict__ z) {
    extern __shared__ char smraw[];
    const uint32_t sb = smem_u32(smraw);
    const int tid  = threadIdx.x;
    const int lane = tid & 31;
    const int wid  = tid >> 5;           // 0..15
    const int mw   = wid >> 1;           // 0..7  (M-warp, 32 rows each)
    const int nw   = wid & 1;            // 0..1  (N-warp, 32 cols each)
    const int gid  = lane >> 2;
    const int tig  = lane & 3;
    const int row0 = blockIdx.x * BM;

    prefetchB(sb, tid, 0);
    asm volatile("cp.async.commit_group;" ::: "memory");

    // ---- prologue: z rows -> fp16 in smem, exact zn (reference rounding) ----
    if (tid < BM) {
        const float4* zr4 = (const float4*)(z + (size_t)(row0 + tid) * E_DIM);
        uint32_t* ap = (uint32_t*)(smraw + SM_A + (uint32_t)tid * ROWSTR);
        float zn = 0.0f;
        #pragma unroll 4
        for (int i = 0; i < 64; i++) {
            float4 v = zr4[i];
            zn = __fadd_rn(zn, __fmul_rn(v.x, v.x));
            zn = __fadd_rn(zn, __fmul_rn(v.y, v.y));
            zn = __fadd_rn(zn, __fmul_rn(v.z, v.z));
            zn = __fadd_rn(zn, __fmul_rn(v.w, v.w));
            __half h0 = __float2half_rn(v.x), h1 = __float2half_rn(v.y);
            __half h2 = __float2half_rn(v.z), h3 = __float2half_rn(v.w);
            ap[i * 2 + 0] = ((uint32_t)__half_as_ushort(h1) << 16) | __half_as_ushort(h0);
            ap[i * 2 + 1] = ((uint32_t)__half_as_ushort(h3) << 16) | __half_as_ushort(h2);
        }
        *(float*)(smraw + SM_ZN + tid * 4) = zn;
        g_zn[row0 + tid] = zn;
    }
    __syncthreads();

    // ldmatrix base addresses
    uint32_t aA[2], bA[2];
    {
        uint32_t arow = (uint32_t)(lane & 15);
        uint32_t ab   = ((uint32_t)(lane >> 4) & 1) * 16;
        #pragma unroll
        for (int mt = 0; mt < 2; mt++)
            aA[mt] = sb + SM_A + ((uint32_t)(mw * 32 + mt * 16) + arow) * ROWSTR + ab;
        #pragma unroll
        for (int p = 0; p < 2; p++)
            bA[p] = sb + SM_B + ((uint32_t)(nw * 32 + p * 16) + arow) * ROWSTR + ab;
    }

    float znv[4];
    #pragma unroll
    for (int sl = 0; sl < 4; sl++) {
        int r = mw * 32 + (sl >> 1) * 16 + (sl & 1) * 8 + gid;
        znv[sl] = *(const float*)(smraw + SM_ZN + r * 4);
    }

    float tb0[4], tb1[4];
    int   ti0[4], ti1[4];
    #pragma unroll
    for (int sl = 0; sl < 4; sl++) { tb0[sl] = 3.4e38f; tb1[sl] = 3.4e38f; ti0[sl] = 0; ti1[sl] = 0; }

    for (int nt = 0; nt < NSTG; nt++) {
        if (nt + 1 < NSTG) {
            prefetchB(sb, tid, nt + 1);
            asm volatile("cp.async.commit_group;" ::: "memory");
            asm volatile("cp.async.wait_group 1;" ::: "memory");
        } else {
            asm volatile("cp.async.wait_group 0;" ::: "memory");
        }
        __syncthreads();

        const uint32_t sof = (uint32_t)(nt & 1) * 33792u;
        uint32_t acc[2][4][2];            // f16x2 accumulators
        #pragma unroll
        for (int mt = 0; mt < 2; mt++)
            #pragma unroll
            for (int n2 = 0; n2 < 4; n2++) { acc[mt][n2][0] = 0u; acc[mt][n2][1] = 0u; }

        #pragma unroll
        for (int kk = 0; kk < 16; kk++) {
            uint32_t kb = (uint32_t)kk * 32;
            uint32_t af[2][4], bw[2][4];
            ldm4(af[0], aA[0] + kb);
            ldm4(af[1], aA[1] + kb);
            ldm4(bw[0], bA[0] + sof + kb);   // n-tiles 0,1: frags {r0,r2},{r1,r3}
            ldm4(bw[1], bA[1] + sof + kb);   // n-tiles 2,3
            #pragma unroll
            for (int mt = 0; mt < 2; mt++)
                #pragma unroll
                for (int p = 0; p < 2; p++)
                    #pragma unroll
                    for (int q = 0; q < 2; q++) {
                        uint32_t bf[2] = { bw[p][q], bw[p][q + 2] };
                        mma16816h(acc[mt][p * 2 + q], af[mt], bf);
                    }
        }

        // distances + per-slot top-2 (columns ascending)
        const float* eNs = (const float*)(smraw + SM_EN + (uint32_t)(nt & 1) * 256);
        #pragma unroll
        for (int n2 = 0; n2 < 4; n2++) {
            int colb = nt * BN + nw * 32 + n2 * 8 + 2 * tig;
            float e0 = eNs[nw * 32 + n2 * 8 + 2 * tig];
            float e1 = eNs[nw * 32 + n2 * 8 + 2 * tig + 1];
            #pragma unroll
            for (int mt = 0; mt < 2; mt++)
                #pragma unroll
                for (int hh = 0; hh < 2; hh++) {
                    int sl = mt * 2 + hh;
                    __half2 hv = *(__half2*)&acc[mt][n2][hh];
                    float dot0 = __half2float(__low2half(hv));
                    float dot1 = __half2float(__high2half(hv));
                    float d0 = __fmaf_rn(-2.0f, dot0, znv[sl] + e0);
                    float d1 = __fmaf_rn(-2.0f, dot1, znv[sl] + e1);
                    if (d0 < tb1[sl]) {
                        if (d0 < tb0[sl]) { tb1[sl]=tb0[sl]; ti1[sl]=ti0[sl]; tb0[sl]=d0; ti0[sl]=colb; }
                        else              { tb1[sl]=d0; ti1[sl]=colb; }
                    }
                    if (d1 < tb1[sl]) {
                        if (d1 < tb0[sl]) { tb1[sl]=tb0[sl]; ti1[sl]=ti0[sl]; tb0[sl]=d1; ti0[sl]=colb+1; }
                        else              { tb1[sl]=d1; ti1[sl]=colb+1; }
                    }
                }
        }
        __syncthreads();
    }

    // ---- candidate table in smem (reuse A region) ----
    float* tD = (float*)smraw;            // [256][16]
    int*   tI = (int*)(smraw + 16384);    // [256][16]
    #pragma unroll
    for (int sl = 0; sl < 4; sl++) {
        int r = mw * 32 + (sl >> 1) * 16 + (sl & 1) * 8 + gid;
        int owner = nw * 4 + tig;         // 0..7
        tD[r * 16 + owner * 2 + 0] = tb0[sl];
        tI[r * 16 + owner * 2 + 0] = ti0[sl];
        tD[r * 16 + owner * 2 + 1] = tb1[sl];
        tI[r * 16 + owner * 2 + 1] = ti1[sl];
    }
    __syncthreads();

    if (tid < BM) {
        float b0 = 3.4e38f, b1 = 3.4e38f;
        int   i0 = 0x7FFFFFFF, i1 = 0x7FFFFFFF;
        #pragma unroll
        for (int q = 0; q < 16; q++) {
            float d = tD[tid * 16 + q];
            int   c = tI[tid * 16 + q];
            if (d < b0 || (d == b0 && c < i0)) { b1 = b0; i1 = i0; b0 = d; i0 = c; }
            else if (d < b1 || (d == b1 && c < i1)) { b1 = d; i1 = c; }
        }
        int r = row0 + tid;
        g_idxi[r] = i0;
        if (__fsub_rn(b1, b0) < TH_MARGIN) {
            int u = atomicAdd(&g_ucount, 1);
            g_urows[u] = r;
            #pragma unroll
            for (int q = 0; q < 16; q++) g_ucand[u * 16 + q] = tI[tid * 16 + q];
        }
    }
}

// ============================================================
// K4: exact rescore of flagged rows (R0-identical numerics), 16 candidates
// ============================================================
__global__ void k_rescore(const float* __restrict__ z, const float* __restrict__ emb) {
    int t = blockIdx.x * blockDim.x + threadIdx.x;
    if (t >= g_ucount) return;
    int r = g_urows[t];
    const float* zr = z + (size_t)r * E_DIM;
    float zn = g_zn[r];
    float bd = 3.4e38f;
    int   bi = 0x7FFFFFFF;
    #pragma unroll 1
    for (int q = 0; q < 16; q++) {
        int c = g_ucand[t * 16 + q];
        const float* er = emb + (size_t)c * E_DIM;
        float acc = 0.0f;
        #pragma unroll 8
        for (int k = 0; k < E_DIM; k++) acc = __fmaf_rn(zr[k], er[k], acc);
        float d = __fsub_rn(__fadd_rn(zn, g_eN[c]), __fmul_rn(2.0f, acc));
        if (d < bd || (d == bd && c < bi)) { bd = d; bi = c; }
    }
    g_idxi[r] = bi;
}

// ============================================================
// K5: epilogue — z_q/straight-through, loss partials, bins/dw atomics
// ============================================================
__global__ __launch_bounds__(256)
void k_epi(const float* __restrict__ z, const float* __restrict__ emb,
           float* __restrict__ out_zq, float* __restrict__ out_idx) {
    __shared__ float sl[256];
    int tid = threadIdx.x;
    int row0 = blockIdx.x * 128;
    int r = row0 + (tid >> 1);
    int h = tid & 1;
    int bi = g_idxi[r];
    if (h == 0) { out_idx[r] = (float)bi; atomicAdd(&g_bins[bi], 1.0f); }
    const float4* zr = (const float4*)(z + (size_t)r * E_DIM + h * 128);
    const float4* er = (const float4*)(emb + (size_t)bi * E_DIM + h * 128);
    float4* oq = (float4*)(out_zq + (size_t)r * E_DIM + h * 128);
    float* dw = g_dw + (size_t)bi * E_DIM + h * 128;
    float ls = 0.0f;
    #pragma unroll 4
    for (int d4 = 0; d4 < 32; d4++) {
        float4 zv = zr[d4];
        float4 ev = er[d4];
        float4 o;
        o.x = __fadd_rn(zv.x, __fsub_rn(ev.x, zv.x));
        o.y = __fadd_rn(zv.y, __fsub_rn(ev.y, zv.y));
        o.z = __fadd_rn(zv.z, __fsub_rn(ev.z, zv.z));
        o.w = __fadd_rn(zv.w, __fsub_rn(ev.w, zv.w));
        oq[d4] = o;
        float dx = __fsub_rn(zv.x, ev.x);
        float dy = __fsub_rn(zv.y, ev.y);
        float dz = __fsub_rn(zv.z, ev.z);
        float dwv = __fsub_rn(zv.w, ev.w);
        ls = __fadd_rn(ls, __fmul_rn(dx, dx));
        ls = __fadd_rn(ls, __fmul_rn(dy, dy));
        ls = __fadd_rn(ls, __fmul_rn(dz, dz));
        ls = __fadd_rn(ls, __fmul_rn(dwv, dwv));
        atomicAdd(dw + d4 * 4 + 0, zv.x);
        atomicAdd(dw + d4 * 4 + 1, zv.y);
        atomicAdd(dw + d4 * 4 + 2, zv.z);
        atomicAdd(dw + d4 * 4 + 3, zv.w);
    }
    sl[tid] = ls;
    __syncthreads();
    for (int s = 128; s > 0; s >>= 1) {
        if (tid < s) sl[tid] += sl[tid + s];
        __syncthreads();
    }
    if (tid == 0) atomicAdd(&g_loss, sl[0]);
}

// ============================================================
// K6: finalize new_embeddings + loss
// ============================================================
__global__ void k_final(float* __restrict__ out_nemb, float* __restrict__ out_loss) {
    int gid = blockIdx.x * blockDim.x + threadIdx.x;
    if (gid == 0) {
        float mean = __fdiv_rn(g_loss, 8388608.0f);
        out_loss[0] = __fmul_rn(0.25f, mean);
    }
    if (gid < N_E * E_DIM) {
        int k = gid >> 8;
        float b = g_bins[k];
        float t1 = __fadd_rn(b, 1e-5f);
        float cl = __fmul_rn(__fdiv_rn(t1, 32768.08192f), 32768.0f);
        out_nemb[gid] = __fdiv_rn(g_dw[gid], cl);
    }
}

// ============================================================
extern "C" void kernel_launch(void* const* d_in, const int* in_sizes, int n_in,
                              void* d_out, int out_size) {
    const float* z   = (const float*)d_in[0];
    const float* emb = (const float*)d_in[1];
    float* out = (float*)d_out;

    cudaFuncSetAttribute(k_mma, cudaFuncAttributeMaxDynamicSharedMemorySize, SM_DYN);

    k_init<<<8192, 256>>>(emb);
    k_prep<<<8192, 256>>>(emb);
    k_mma<<<N_TOK / BM, 512, SM_DYN>>>(z);
    k_rescore<<<128, 256>>>(z, emb);
    k_epi<<<N_TOK / 128, 256>>>(z, emb, out + OFF_ZQ, out + OFF_IDX);
    k_final<<<8192, 256>>>(out + OFF_NEMB, out + OFF_LOSS);
}